// round 3
// baseline (speedup 1.0000x reference)
#include <cuda_runtime.h>
#include <cuda_bf16.h>
#include <math.h>

#define BB   2
#define CC   64
#define NPTS 20000
#define KK   16
#define CO   64
#define NODES (BB * NPTS)

// Scratch (device globals: allocation-free rule)
__device__ float g_U[NODES * CO];     // (W1-W2) @ x   per node
__device__ float g_V[NODES * CO];     // W2      @ x   per node
__device__ float g_posT[NODES * 4];   // pos transposed to [node][4]

// Packed fp32x2 FMA (Blackwell): d = a*b + d, two fp32 lanes per instruction.
#define FMA2(d, a, b) \
    asm("fma.rn.f32x2 %0, %1, %2, %0;" : "+l"(d) : "l"(a), "l"(b))

__device__ __forceinline__ unsigned long long pack2(float lo, float hi) {
    unsigned long long r;
    asm("mov.b64 %0, {%1, %2};" : "=l"(r) : "r"(__float_as_uint(lo)), "r"(__float_as_uint(hi)));
    return r;
}

// ---------------------------------------------------------------------------
// Kernel 1: per-node transform u = (W1-W2)x, v = W2 x, fused pos transpose.
// Block = 256 threads = 64 nodes x 4 output-chunks of 32.
//   sW[c][o]  (o<64 -> (W1-W2)^T, o>=64 -> W2^T)   : 32 KB
//   sx[c][nl] (x tile for this block's 64 nodes)   : 16 KB
// Thread (q = tid>>6, nl = tid&63) computes outputs [q*32, q*32+32) for
// node = base+nl, as 16 packed f32x2 accumulators.
// ---------------------------------------------------------------------------
__global__ __launch_bounds__(256) void uv_kernel(const float* __restrict__ x,
                                                 const float* __restrict__ pos,
                                                 const float* __restrict__ W) {
    __shared__ float sW[64 * 128];   // 32 KB
    __shared__ float sx[64 * 64];    // 16 KB  (total = 48 KB static, the max)

    int tid  = threadIdx.x;
    int base = blockIdx.x * 64;

    // Stage combined weights, transposed to [c][o].
    for (int i = tid; i < 64 * 128; i += 256) {
        int c = i >> 7, o = i & 127;
        float w;
        if (o < 64)
            w = W[o * 128 + c] - W[o * 128 + 64 + c];   // W1 - W2
        else
            w = W[(o - 64) * 128 + 64 + c];             // W2
        sW[c * 128 + o] = w;
    }

    // Stage x tile: sx[c][nl] = x[b, c, n]. Lanes cover consecutive nl ->
    // coalesced global reads.
#pragma unroll
    for (int j = 0; j < 16; ++j) {
        int i  = tid + j * 256;
        int c  = i >> 6, nl = i & 63;
        int node = base + nl;
        int b  = node / NPTS;
        int n  = node - b * NPTS;
        sx[c * 64 + nl] = x[b * CC * NPTS + c * NPTS + n];
    }

    // pos transpose handled by the first 64 threads (one node each).
    if (tid < 64) {
        int node = base + tid;
        int b = node / NPTS;
        int n = node - b * NPTS;
        const float* pb = pos + b * 3 * NPTS + n;
        float4 p;
        p.x = pb[0];
        p.y = pb[NPTS];
        p.z = pb[2 * NPTS];
        p.w = 0.0f;
        reinterpret_cast<float4*>(g_posT)[node] = p;
    }
    __syncthreads();

    int q  = tid >> 6;      // output chunk 0..3
    int nl = tid & 63;      // node within block
    int node = base + nl;

    unsigned long long acc[16];
#pragma unroll
    for (int t = 0; t < 16; ++t) acc[t] = 0ull;   // (0.f, 0.f)

    const float* xcol = sx + nl;
    const float* wrow = sW + q * 32;

#pragma unroll 4
    for (int c = 0; c < 64; ++c) {
        float xv = xcol[c * 64];
        unsigned long long xp = pack2(xv, xv);
        const ulonglong2* wp = reinterpret_cast<const ulonglong2*>(wrow + c * 128);
#pragma unroll
        for (int t = 0; t < 8; ++t) {
            ulonglong2 w = wp[t];           // 4 weights = 2 packed operands
            FMA2(acc[2 * t],     w.x, xp);
            FMA2(acc[2 * t + 1], w.y, xp);
        }
    }

    // chunks 0,1 -> U[node][0:64); chunks 2,3 -> V[node][0:64)
    float* dstf = (q < 2) ? (g_U + node * 64 + q * 32)
                          : (g_V + node * 64 + (q - 2) * 32);
    ulonglong2* dst = reinterpret_cast<ulonglong2*>(dstf);
#pragma unroll
    for (int t = 0; t < 8; ++t)
        dst[t] = make_ulonglong2(acc[2 * t], acc[2 * t + 1]);
}

// ---------------------------------------------------------------------------
// Kernel 2: per-edge combine + suppression + max over K. (unchanged from R2)
// One warp per point, 8 warps/block. Lanes 0..15 precompute indices and the
// suppression factor for their k (distributed via shfl). Gathers prefetched
// in chunks of 4. Shared staging for coalesced [CO, N] stores.
// ---------------------------------------------------------------------------
__global__ __launch_bounds__(256) void edge_kernel(const int* __restrict__ ei,
                                                   const float* __restrict__ bias,
                                                   float* __restrict__ out) {
    __shared__ float sm[8 * 66];

    int tid  = threadIdx.x;
    int warp = tid >> 5;
    int lane = tid & 31;

    int g = blockIdx.x * 8 + warp;   // 20000 % 8 == 0 -> block never crosses batch
    int b = g / NPTS;
    int n = g - b * NPTS;

    const int* e0 = ei + (b * NPTS + n) * KK;                    // neighbor idx
    const int* e1 = ei + (BB * NPTS * KK) + (b * NPTS + n) * KK; // center idx

    const float*  Ub = g_U + b * NPTS * 64;
    const float*  Vb = g_V + b * NPTS * 64;
    const float4* Pb = reinterpret_cast<const float4*>(g_posT) + b * NPTS;

    // lanes 0..15: own one k each -> indices + suppression factor
    int   i0l = 0, i1l = 0;
    float sl  = 0.0f;
    if (lane < KK) {
        i0l = e0[lane];
        i1l = e1[lane];
        float4 p1 = Pb[i1l];
        float4 p0 = Pb[i0l];
        float dx = p1.x - p0.x, dy = p1.y - p0.y, dz = p1.z - p0.z;
        float dis = sqrtf(dx * dx + dy * dy + dz * dz);
        sl = 2.0f / (1.0f + __expf(dis));   // 2*sigmoid(-dis)
    }

    float2 bb = reinterpret_cast<const float2*>(bias)[lane];

    float m0 = 0.0f, m1 = 0.0f;  // relu * positive factor => result >= 0

#pragma unroll
    for (int k0 = 0; k0 < KK; k0 += 4) {
        float2 u[4], v[4];
        float  s[4];
#pragma unroll
        for (int j = 0; j < 4; ++j) {
            int i1 = __shfl_sync(0xFFFFFFFFu, i1l, k0 + j);
            int i0 = __shfl_sync(0xFFFFFFFFu, i0l, k0 + j);
            s[j]   = __shfl_sync(0xFFFFFFFFu, sl,  k0 + j);
            u[j] = reinterpret_cast<const float2*>(Ub + i1 * 64)[lane];
            v[j] = reinterpret_cast<const float2*>(Vb + i0 * 64)[lane];
        }
#pragma unroll
        for (int j = 0; j < 4; ++j) {
            float y0 = fmaxf(u[j].x + v[j].x + bb.x, 0.0f) * s[j];
            float y1 = fmaxf(u[j].y + v[j].y + bb.y, 0.0f) * s[j];
            m0 = fmaxf(m0, y0);
            m1 = fmaxf(m1, y1);
        }
    }

    reinterpret_cast<float2*>(sm + warp * 66)[lane] = make_float2(m0, m1);
    __syncthreads();

    int base = blockIdx.x * 8;
    int b2 = base / NPTS;
    int n0 = base - b2 * NPTS;
#pragma unroll
    for (int e = tid; e < CO * 8; e += 256) {
        int o  = e >> 3;
        int nn = e & 7;
        out[(b2 * CO + o) * NPTS + n0 + nn] = sm[nn * 66 + o];
    }
}

extern "C" void kernel_launch(void* const* d_in, const int* in_sizes, int n_in,
                              void* d_out, int out_size) {
    const float* x    = (const float*)d_in[0];
    const int*   ei   = (const int*)d_in[1];
    const float* pos  = (const float*)d_in[2];
    const float* W    = (const float*)d_in[3];
    const float* bias = (const float*)d_in[4];
    float* out = (float*)d_out;

    uv_kernel<<<NODES / 64, 256>>>(x, pos, W);
    edge_kernel<<<NODES / 8, 256>>>(ei, bias, out);
}

// round 4
// speedup vs baseline: 1.1021x; 1.1021x over previous
#include <cuda_runtime.h>
#include <cuda_bf16.h>
#include <math.h>

#define BB   2
#define CC   64
#define NPTS 20000
#define KK   16
#define CO   64
#define NODES (BB * NPTS)

// Scratch (device globals: allocation-free rule)
__device__ float g_U[NODES * CO];     // (W1-W2) @ x   per node
__device__ float g_V[NODES * CO];     // W2      @ x   per node
__device__ float g_posT[NODES * 4];   // pos transposed to [node][4]

// ---------------------------------------------------------------------------
// Kernel 1: per-node transform u = (W1-W2)x, v = W2 x, fused pos transpose.
// Block = 256 threads = 64-node tile.
//   sW[c][o]  (o<64 -> (W1-W2)^T, o>=64 -> W2^T)   : 32 KB
//   sx[c][nl] (x tile for this block's 64 nodes)   : 16 KB
// Thread (og = tid>>5 in 0..7, ng = tid&31) computes outputs
// [og*16, og*16+16) for the two nodes base+2*ng, base+2*ng+1.
// Scalar FMA only: 32 acc regs, 16 weight regs live per c-iter.
// Weight LDS broadcasts within a warp (all lanes share og).
// ---------------------------------------------------------------------------
__global__ __launch_bounds__(256) void uv_kernel(const float* __restrict__ x,
                                                 const float* __restrict__ pos,
                                                 const float* __restrict__ W) {
    __shared__ float sW[64 * 128];   // 32 KB
    __shared__ float sx[64 * 64];    // 16 KB

    int tid  = threadIdx.x;
    int base = blockIdx.x * 64;

    // Stage combined weights, transposed to [c][o].
    for (int i = tid; i < 64 * 128; i += 256) {
        int c = i >> 7, o = i & 127;
        float w;
        if (o < 64)
            w = W[o * 128 + c] - W[o * 128 + 64 + c];   // W1 - W2
        else
            w = W[(o - 64) * 128 + 64 + c];             // W2
        sW[c * 128 + o] = w;
    }

    // Stage x tile: sx[c][nl] = x[b, c, n] (coalesced over nl).
#pragma unroll
    for (int j = 0; j < 16; ++j) {
        int i  = tid + j * 256;
        int c  = i >> 6, nl = i & 63;
        int node = base + nl;
        int b  = node / NPTS;
        int n  = node - b * NPTS;
        sx[c * 64 + nl] = x[b * CC * NPTS + c * NPTS + n];
    }

    // pos transpose by the first 64 threads (one node each).
    if (tid < 64) {
        int node = base + tid;
        int b = node / NPTS;
        int n = node - b * NPTS;
        const float* pb = pos + b * 3 * NPTS + n;
        float4 p;
        p.x = pb[0];
        p.y = pb[NPTS];
        p.z = pb[2 * NPTS];
        p.w = 0.0f;
        reinterpret_cast<float4*>(g_posT)[node] = p;
    }
    __syncthreads();

    int og = tid >> 5;          // output group 0..7 (16 outputs each)
    int ng = tid & 31;          // node pair 0..31

    float a0[16], a1[16];       // acc for node0 / node1
#pragma unroll
    for (int t = 0; t < 16; ++t) { a0[t] = 0.0f; a1[t] = 0.0f; }

    const float2* xcol = reinterpret_cast<const float2*>(sx) + ng;   // stride 32 float2 per c
    const float4* wrow = reinterpret_cast<const float4*>(sW + og * 16);

#pragma unroll 2
    for (int c = 0; c < 64; ++c) {
        float2 xx = xcol[c * 32];
        float4 w0 = wrow[c * 32 + 0];
        float4 w1 = wrow[c * 32 + 1];
        float4 w2 = wrow[c * 32 + 2];
        float4 w3 = wrow[c * 32 + 3];
        a0[0]  = fmaf(w0.x, xx.x, a0[0]);   a1[0]  = fmaf(w0.x, xx.y, a1[0]);
        a0[1]  = fmaf(w0.y, xx.x, a0[1]);   a1[1]  = fmaf(w0.y, xx.y, a1[1]);
        a0[2]  = fmaf(w0.z, xx.x, a0[2]);   a1[2]  = fmaf(w0.z, xx.y, a1[2]);
        a0[3]  = fmaf(w0.w, xx.x, a0[3]);   a1[3]  = fmaf(w0.w, xx.y, a1[3]);
        a0[4]  = fmaf(w1.x, xx.x, a0[4]);   a1[4]  = fmaf(w1.x, xx.y, a1[4]);
        a0[5]  = fmaf(w1.y, xx.x, a0[5]);   a1[5]  = fmaf(w1.y, xx.y, a1[5]);
        a0[6]  = fmaf(w1.z, xx.x, a0[6]);   a1[6]  = fmaf(w1.z, xx.y, a1[6]);
        a0[7]  = fmaf(w1.w, xx.x, a0[7]);   a1[7]  = fmaf(w1.w, xx.y, a1[7]);
        a0[8]  = fmaf(w2.x, xx.x, a0[8]);   a1[8]  = fmaf(w2.x, xx.y, a1[8]);
        a0[9]  = fmaf(w2.y, xx.x, a0[9]);   a1[9]  = fmaf(w2.y, xx.y, a1[9]);
        a0[10] = fmaf(w2.z, xx.x, a0[10]);  a1[10] = fmaf(w2.z, xx.y, a1[10]);
        a0[11] = fmaf(w2.w, xx.x, a0[11]);  a1[11] = fmaf(w2.w, xx.y, a1[11]);
        a0[12] = fmaf(w3.x, xx.x, a0[12]);  a1[12] = fmaf(w3.x, xx.y, a1[12]);
        a0[13] = fmaf(w3.y, xx.x, a0[13]);  a1[13] = fmaf(w3.y, xx.y, a1[13]);
        a0[14] = fmaf(w3.z, xx.x, a0[14]);  a1[14] = fmaf(w3.z, xx.y, a1[14]);
        a0[15] = fmaf(w3.w, xx.x, a0[15]);  a1[15] = fmaf(w3.w, xx.y, a1[15]);
    }

    // og 0..3 -> U[node][og*16 ..), og 4..7 -> V[node][(og-4)*16 ..)
    int node0 = base + 2 * ng;
    float* d0 = (og < 4) ? (g_U + node0 * 64 + og * 16)
                         : (g_V + node0 * 64 + (og - 4) * 16);
    float* d1 = d0 + 64;
    float4* d04 = reinterpret_cast<float4*>(d0);
    float4* d14 = reinterpret_cast<float4*>(d1);
#pragma unroll
    for (int t = 0; t < 4; ++t) {
        d04[t] = make_float4(a0[4 * t], a0[4 * t + 1], a0[4 * t + 2], a0[4 * t + 3]);
        d14[t] = make_float4(a1[4 * t], a1[4 * t + 1], a1[4 * t + 2], a1[4 * t + 3]);
    }
}

// ---------------------------------------------------------------------------
// Kernel 2: per-edge combine + suppression + max over K. (unchanged from R2)
// ---------------------------------------------------------------------------
__global__ __launch_bounds__(256) void edge_kernel(const int* __restrict__ ei,
                                                   const float* __restrict__ bias,
                                                   float* __restrict__ out) {
    __shared__ float sm[8 * 66];

    int tid  = threadIdx.x;
    int warp = tid >> 5;
    int lane = tid & 31;

    int g = blockIdx.x * 8 + warp;   // 20000 % 8 == 0 -> block never crosses batch
    int b = g / NPTS;
    int n = g - b * NPTS;

    const int* e0 = ei + (b * NPTS + n) * KK;                    // neighbor idx
    const int* e1 = ei + (BB * NPTS * KK) + (b * NPTS + n) * KK; // center idx

    const float*  Ub = g_U + b * NPTS * 64;
    const float*  Vb = g_V + b * NPTS * 64;
    const float4* Pb = reinterpret_cast<const float4*>(g_posT) + b * NPTS;

    int   i0l = 0, i1l = 0;
    float sl  = 0.0f;
    if (lane < KK) {
        i0l = e0[lane];
        i1l = e1[lane];
        float4 p1 = Pb[i1l];
        float4 p0 = Pb[i0l];
        float dx = p1.x - p0.x, dy = p1.y - p0.y, dz = p1.z - p0.z;
        float dis = sqrtf(dx * dx + dy * dy + dz * dz);
        sl = 2.0f / (1.0f + __expf(dis));   // 2*sigmoid(-dis)
    }

    float2 bb = reinterpret_cast<const float2*>(bias)[lane];

    float m0 = 0.0f, m1 = 0.0f;

#pragma unroll
    for (int k0 = 0; k0 < KK; k0 += 4) {
        float2 u[4], v[4];
        float  s[4];
#pragma unroll
        for (int j = 0; j < 4; ++j) {
            int i1 = __shfl_sync(0xFFFFFFFFu, i1l, k0 + j);
            int i0 = __shfl_sync(0xFFFFFFFFu, i0l, k0 + j);
            s[j]   = __shfl_sync(0xFFFFFFFFu, sl,  k0 + j);
            u[j] = reinterpret_cast<const float2*>(Ub + i1 * 64)[lane];
            v[j] = reinterpret_cast<const float2*>(Vb + i0 * 64)[lane];
        }
#pragma unroll
        for (int j = 0; j < 4; ++j) {
            float y0 = fmaxf(u[j].x + v[j].x + bb.x, 0.0f) * s[j];
            float y1 = fmaxf(u[j].y + v[j].y + bb.y, 0.0f) * s[j];
            m0 = fmaxf(m0, y0);
            m1 = fmaxf(m1, y1);
        }
    }

    reinterpret_cast<float2*>(sm + warp * 66)[lane] = make_float2(m0, m1);
    __syncthreads();

    int base = blockIdx.x * 8;
    int b2 = base / NPTS;
    int n0 = base - b2 * NPTS;
#pragma unroll
    for (int e = tid; e < CO * 8; e += 256) {
        int o  = e >> 3;
        int nn = e & 7;
        out[(b2 * CO + o) * NPTS + n0 + nn] = sm[nn * 66 + o];
    }
}

extern "C" void kernel_launch(void* const* d_in, const int* in_sizes, int n_in,
                              void* d_out, int out_size) {
    const float* x    = (const float*)d_in[0];
    const int*   ei   = (const int*)d_in[1];
    const float* pos  = (const float*)d_in[2];
    const float* W    = (const float*)d_in[3];
    const float* bias = (const float*)d_in[4];
    float* out = (float*)d_out;

    uv_kernel<<<NODES / 64, 256>>>(x, pos, W);
    edge_kernel<<<NODES / 8, 256>>>(ei, bias, out);
}

// round 5
// speedup vs baseline: 1.5106x; 1.3707x over previous
#include <cuda_runtime.h>
#include <cuda_bf16.h>
#include <math.h>

#define BB   2
#define CC   64
#define NPTS 20000
#define KK   16
#define CO   64
#define NODES (BB * NPTS)

// Scratch (device globals: allocation-free rule)
__device__ float g_U[NODES * CO];     // (W1-W2) @ x   per node
__device__ float g_V[NODES * CO];     // W2      @ x   per node
__device__ float g_posT[NODES * 4];   // pos transposed to [node][4]
__device__ float g_Wc[64 * 128];      // combined weights, [c][o] layout

// ---------------------------------------------------------------------------
// Kernel 0: weight prep (single block). g_Wc[c][o] = (W1-W2)^T for o<64,
// W2^T for o>=64. Reads of W are coalesced (consecutive tid -> consecutive c);
// scattered stores are cheap (no result dependency).
// ---------------------------------------------------------------------------
__global__ __launch_bounds__(256) void wprep_kernel(const float* __restrict__ W) {
    int tid = threadIdx.x;
#pragma unroll
    for (int i = tid; i < 64 * 64; i += 256) {
        int o = i >> 6, c = i & 63;
        float w1 = W[o * 128 + c];        // coalesced over c
        float w2 = W[o * 128 + 64 + c];   // coalesced over c
        g_Wc[c * 128 + o]      = w1 - w2;
        g_Wc[c * 128 + 64 + o] = w2;
    }
}

// ---------------------------------------------------------------------------
// Kernel 1: per-node transform u = (W1-W2)x, v = W2 x, fused pos transpose.
// Block = 256 threads = 64-node tile.
//   sW[c][o] : 32 KB  (float4 copy from g_Wc, fully coalesced)
//   sx[c][nl]: 16 KB  (x tile, coalesced)
// Thread (og = tid>>5 in 0..7, ng = tid&31) computes outputs
// [og*16, og*16+16) for nodes base+2*ng, base+2*ng+1. Scalar FMA.
// ---------------------------------------------------------------------------
__global__ __launch_bounds__(256) void uv_kernel(const float* __restrict__ x,
                                                 const float* __restrict__ pos) {
    __shared__ float sW[64 * 128];   // 32 KB
    __shared__ float sx[64 * 64];    // 16 KB

    int tid  = threadIdx.x;
    int base = blockIdx.x * 64;

    // Stage combined weights: straight float4 copy, coalesced.
    {
        const float4* src = reinterpret_cast<const float4*>(g_Wc);
        float4*       dst = reinterpret_cast<float4*>(sW);
#pragma unroll
        for (int i = tid; i < 64 * 128 / 4; i += 256) dst[i] = src[i];
    }

    // Stage x tile: sx[c][nl] = x[b, c, n] (coalesced over nl).
#pragma unroll
    for (int j = 0; j < 16; ++j) {
        int i  = tid + j * 256;
        int c  = i >> 6, nl = i & 63;
        int node = base + nl;
        int b  = node / NPTS;
        int n  = node - b * NPTS;
        sx[c * 64 + nl] = x[b * CC * NPTS + c * NPTS + n];
    }

    // pos transpose by the first 64 threads (one node each).
    if (tid < 64) {
        int node = base + tid;
        int b = node / NPTS;
        int n = node - b * NPTS;
        const float* pb = pos + b * 3 * NPTS + n;
        float4 p;
        p.x = pb[0];
        p.y = pb[NPTS];
        p.z = pb[2 * NPTS];
        p.w = 0.0f;
        reinterpret_cast<float4*>(g_posT)[node] = p;
    }
    __syncthreads();

    int og = tid >> 5;          // output group 0..7 (16 outputs each)
    int ng = tid & 31;          // node pair 0..31

    float a0[16], a1[16];       // acc for node0 / node1
#pragma unroll
    for (int t = 0; t < 16; ++t) { a0[t] = 0.0f; a1[t] = 0.0f; }

    const float2* xcol = reinterpret_cast<const float2*>(sx) + ng;
    const float4* wrow = reinterpret_cast<const float4*>(sW + og * 16);

#pragma unroll 2
    for (int c = 0; c < 64; ++c) {
        float2 xx = xcol[c * 32];
        float4 w0 = wrow[c * 32 + 0];
        float4 w1 = wrow[c * 32 + 1];
        float4 w2 = wrow[c * 32 + 2];
        float4 w3 = wrow[c * 32 + 3];
        a0[0]  = fmaf(w0.x, xx.x, a0[0]);   a1[0]  = fmaf(w0.x, xx.y, a1[0]);
        a0[1]  = fmaf(w0.y, xx.x, a0[1]);   a1[1]  = fmaf(w0.y, xx.y, a1[1]);
        a0[2]  = fmaf(w0.z, xx.x, a0[2]);   a1[2]  = fmaf(w0.z, xx.y, a1[2]);
        a0[3]  = fmaf(w0.w, xx.x, a0[3]);   a1[3]  = fmaf(w0.w, xx.y, a1[3]);
        a0[4]  = fmaf(w1.x, xx.x, a0[4]);   a1[4]  = fmaf(w1.x, xx.y, a1[4]);
        a0[5]  = fmaf(w1.y, xx.x, a0[5]);   a1[5]  = fmaf(w1.y, xx.y, a1[5]);
        a0[6]  = fmaf(w1.z, xx.x, a0[6]);   a1[6]  = fmaf(w1.z, xx.y, a1[6]);
        a0[7]  = fmaf(w1.w, xx.x, a0[7]);   a1[7]  = fmaf(w1.w, xx.y, a1[7]);
        a0[8]  = fmaf(w2.x, xx.x, a0[8]);   a1[8]  = fmaf(w2.x, xx.y, a1[8]);
        a0[9]  = fmaf(w2.y, xx.x, a0[9]);   a1[9]  = fmaf(w2.y, xx.y, a1[9]);
        a0[10] = fmaf(w2.z, xx.x, a0[10]);  a1[10] = fmaf(w2.z, xx.y, a1[10]);
        a0[11] = fmaf(w2.w, xx.x, a0[11]);  a1[11] = fmaf(w2.w, xx.y, a1[11]);
        a0[12] = fmaf(w3.x, xx.x, a0[12]);  a1[12] = fmaf(w3.x, xx.y, a1[12]);
        a0[13] = fmaf(w3.y, xx.x, a0[13]);  a1[13] = fmaf(w3.y, xx.y, a1[13]);
        a0[14] = fmaf(w3.z, xx.x, a0[14]);  a1[14] = fmaf(w3.z, xx.y, a1[14]);
        a0[15] = fmaf(w3.w, xx.x, a0[15]);  a1[15] = fmaf(w3.w, xx.y, a1[15]);
    }

    // og 0..3 -> U[node][og*16 ..), og 4..7 -> V[node][(og-4)*16 ..)
    int node0 = base + 2 * ng;
    float* d0 = (og < 4) ? (g_U + node0 * 64 + og * 16)
                         : (g_V + node0 * 64 + (og - 4) * 16);
    float* d1 = d0 + 64;
    float4* d04 = reinterpret_cast<float4*>(d0);
    float4* d14 = reinterpret_cast<float4*>(d1);
#pragma unroll
    for (int t = 0; t < 4; ++t) {
        d04[t] = make_float4(a0[4 * t], a0[4 * t + 1], a0[4 * t + 2], a0[4 * t + 3]);
        d14[t] = make_float4(a1[4 * t], a1[4 * t + 1], a1[4 * t + 2], a1[4 * t + 3]);
    }
}

// ---------------------------------------------------------------------------
// Kernel 2: per-edge combine + suppression + max over K. (unchanged — this
// kernel sits at the L2/LTS throughput roofline for fp32 gathers.)
// ---------------------------------------------------------------------------
__global__ __launch_bounds__(256) void edge_kernel(const int* __restrict__ ei,
                                                   const float* __restrict__ bias,
                                                   float* __restrict__ out) {
    __shared__ float sm[8 * 66];

    int tid  = threadIdx.x;
    int warp = tid >> 5;
    int lane = tid & 31;

    int g = blockIdx.x * 8 + warp;   // 20000 % 8 == 0 -> block never crosses batch
    int b = g / NPTS;
    int n = g - b * NPTS;

    const int* e0 = ei + (b * NPTS + n) * KK;                    // neighbor idx
    const int* e1 = ei + (BB * NPTS * KK) + (b * NPTS + n) * KK; // center idx

    const float*  Ub = g_U + b * NPTS * 64;
    const float*  Vb = g_V + b * NPTS * 64;
    const float4* Pb = reinterpret_cast<const float4*>(g_posT) + b * NPTS;

    int   i0l = 0, i1l = 0;
    float sl  = 0.0f;
    if (lane < KK) {
        i0l = e0[lane];
        i1l = e1[lane];
        float4 p1 = Pb[i1l];
        float4 p0 = Pb[i0l];
        float dx = p1.x - p0.x, dy = p1.y - p0.y, dz = p1.z - p0.z;
        float dis = sqrtf(dx * dx + dy * dy + dz * dz);
        sl = 2.0f / (1.0f + __expf(dis));   // 2*sigmoid(-dis)
    }

    float2 bb = reinterpret_cast<const float2*>(bias)[lane];

    float m0 = 0.0f, m1 = 0.0f;

#pragma unroll
    for (int k0 = 0; k0 < KK; k0 += 4) {
        float2 u[4], v[4];
        float  s[4];
#pragma unroll
        for (int j = 0; j < 4; ++j) {
            int i1 = __shfl_sync(0xFFFFFFFFu, i1l, k0 + j);
            int i0 = __shfl_sync(0xFFFFFFFFu, i0l, k0 + j);
            s[j]   = __shfl_sync(0xFFFFFFFFu, sl,  k0 + j);
            u[j] = reinterpret_cast<const float2*>(Ub + i1 * 64)[lane];
            v[j] = reinterpret_cast<const float2*>(Vb + i0 * 64)[lane];
        }
#pragma unroll
        for (int j = 0; j < 4; ++j) {
            float y0 = fmaxf(u[j].x + v[j].x + bb.x, 0.0f) * s[j];
            float y1 = fmaxf(u[j].y + v[j].y + bb.y, 0.0f) * s[j];
            m0 = fmaxf(m0, y0);
            m1 = fmaxf(m1, y1);
        }
    }

    reinterpret_cast<float2*>(sm + warp * 66)[lane] = make_float2(m0, m1);
    __syncthreads();

    int base = blockIdx.x * 8;
    int b2 = base / NPTS;
    int n0 = base - b2 * NPTS;
#pragma unroll
    for (int e = tid; e < CO * 8; e += 256) {
        int o  = e >> 3;
        int nn = e & 7;
        out[(b2 * CO + o) * NPTS + n0 + nn] = sm[nn * 66 + o];
    }
}

extern "C" void kernel_launch(void* const* d_in, const int* in_sizes, int n_in,
                              void* d_out, int out_size) {
    const float* x    = (const float*)d_in[0];
    const int*   ei   = (const int*)d_in[1];
    const float* pos  = (const float*)d_in[2];
    const float* W    = (const float*)d_in[3];
    const float* bias = (const float*)d_in[4];
    float* out = (float*)d_out;

    wprep_kernel<<<1, 256>>>(W);
    uv_kernel<<<NODES / 64, 256>>>(x, pos);
    edge_kernel<<<NODES / 8, 256>>>(ei, bias, out);
}

// round 6
// speedup vs baseline: 1.7585x; 1.1641x over previous
#include <cuda_runtime.h>
#include <cuda_fp16.h>
#include <math.h>

#define BB   2
#define CC   64
#define NPTS 20000
#define KK   16
#define CO   64
#define NODES (BB * NPTS)

// Scratch (device globals: allocation-free rule)
// U/V stored as fp16 rows of 64 halves (= 8 uint4) per node: halves edge-kernel
// gather traffic, which sits at the L2/LTS throughput cap.
__device__ uint4 g_U[NODES * 8];      // (W1-W2) @ x   per node, fp16
__device__ uint4 g_V[NODES * 8];      // W2      @ x   per node, fp16
__device__ float g_posT[NODES * 4];   // pos transposed to [node][4]
__device__ float g_Wc[64 * 128];      // combined weights, [c][o] layout

__device__ __forceinline__ unsigned f2h2(float lo, float hi) {
    __half2 h = __floats2half2_rn(lo, hi);
    return *reinterpret_cast<unsigned*>(&h);
}

// ---------------------------------------------------------------------------
// Kernel 0: weight prep. 16 blocks x 256 threads, one element each (the
// single-block version was latency-bound at 9.3us). Coalesced reads of W.
// ---------------------------------------------------------------------------
__global__ __launch_bounds__(256) void wprep_kernel(const float* __restrict__ W) {
    int i = blockIdx.x * 256 + threadIdx.x;   // i in [0, 4096)
    int o = i >> 6, c = i & 63;
    float w1 = W[o * 128 + c];        // coalesced over c
    float w2 = W[o * 128 + 64 + c];
    g_Wc[c * 128 + o]      = w1 - w2;
    g_Wc[c * 128 + 64 + o] = w2;
}

// ---------------------------------------------------------------------------
// Kernel 1: per-node transform u = (W1-W2)x, v = W2 x, fused pos transpose.
// Block = 256 threads = 64-node tile. fp32 math, fp16 output.
//   sW[c][o] : 32 KB  (float4 copy from g_Wc, fully coalesced)
//   sx[c][nl]: 16 KB  (x tile, coalesced)
// Thread (og = tid>>5, ng = tid&31) computes outputs [og*16, og*16+16)
// for nodes base+2*ng, base+2*ng+1. Scalar FMA (at the fma-pipe floor).
// ---------------------------------------------------------------------------
__global__ __launch_bounds__(256) void uv_kernel(const float* __restrict__ x,
                                                 const float* __restrict__ pos) {
    __shared__ float sW[64 * 128];   // 32 KB
    __shared__ float sx[64 * 64];    // 16 KB

    int tid  = threadIdx.x;
    int base = blockIdx.x * 64;

    // Stage combined weights: straight float4 copy, coalesced.
    {
        const float4* src = reinterpret_cast<const float4*>(g_Wc);
        float4*       dst = reinterpret_cast<float4*>(sW);
#pragma unroll
        for (int i = tid; i < 64 * 128 / 4; i += 256) dst[i] = src[i];
    }

    // Stage x tile: sx[c][nl] = x[b, c, n] (coalesced over nl).
#pragma unroll
    for (int j = 0; j < 16; ++j) {
        int i  = tid + j * 256;
        int c  = i >> 6, nl = i & 63;
        int node = base + nl;
        int b  = node / NPTS;
        int n  = node - b * NPTS;
        sx[c * 64 + nl] = x[b * CC * NPTS + c * NPTS + n];
    }

    // pos transpose by the first 64 threads (one node each).
    if (tid < 64) {
        int node = base + tid;
        int b = node / NPTS;
        int n = node - b * NPTS;
        const float* pb = pos + b * 3 * NPTS + n;
        float4 p;
        p.x = pb[0];
        p.y = pb[NPTS];
        p.z = pb[2 * NPTS];
        p.w = 0.0f;
        reinterpret_cast<float4*>(g_posT)[node] = p;
    }
    __syncthreads();

    int og = tid >> 5;          // output group 0..7 (16 outputs each)
    int ng = tid & 31;          // node pair 0..31

    float a0[16], a1[16];       // acc for node0 / node1
#pragma unroll
    for (int t = 0; t < 16; ++t) { a0[t] = 0.0f; a1[t] = 0.0f; }

    const float2* xcol = reinterpret_cast<const float2*>(sx) + ng;
    const float4* wrow = reinterpret_cast<const float4*>(sW + og * 16);

#pragma unroll 2
    for (int c = 0; c < 64; ++c) {
        float2 xx = xcol[c * 32];
        float4 w0 = wrow[c * 32 + 0];
        float4 w1 = wrow[c * 32 + 1];
        float4 w2 = wrow[c * 32 + 2];
        float4 w3 = wrow[c * 32 + 3];
        a0[0]  = fmaf(w0.x, xx.x, a0[0]);   a1[0]  = fmaf(w0.x, xx.y, a1[0]);
        a0[1]  = fmaf(w0.y, xx.x, a0[1]);   a1[1]  = fmaf(w0.y, xx.y, a1[1]);
        a0[2]  = fmaf(w0.z, xx.x, a0[2]);   a1[2]  = fmaf(w0.z, xx.y, a1[2]);
        a0[3]  = fmaf(w0.w, xx.x, a0[3]);   a1[3]  = fmaf(w0.w, xx.y, a1[3]);
        a0[4]  = fmaf(w1.x, xx.x, a0[4]);   a1[4]  = fmaf(w1.x, xx.y, a1[4]);
        a0[5]  = fmaf(w1.y, xx.x, a0[5]);   a1[5]  = fmaf(w1.y, xx.y, a1[5]);
        a0[6]  = fmaf(w1.z, xx.x, a0[6]);   a1[6]  = fmaf(w1.z, xx.y, a1[6]);
        a0[7]  = fmaf(w1.w, xx.x, a0[7]);   a1[7]  = fmaf(w1.w, xx.y, a1[7]);
        a0[8]  = fmaf(w2.x, xx.x, a0[8]);   a1[8]  = fmaf(w2.x, xx.y, a1[8]);
        a0[9]  = fmaf(w2.y, xx.x, a0[9]);   a1[9]  = fmaf(w2.y, xx.y, a1[9]);
        a0[10] = fmaf(w2.z, xx.x, a0[10]);  a1[10] = fmaf(w2.z, xx.y, a1[10]);
        a0[11] = fmaf(w2.w, xx.x, a0[11]);  a1[11] = fmaf(w2.w, xx.y, a1[11]);
        a0[12] = fmaf(w3.x, xx.x, a0[12]);  a1[12] = fmaf(w3.x, xx.y, a1[12]);
        a0[13] = fmaf(w3.y, xx.x, a0[13]);  a1[13] = fmaf(w3.y, xx.y, a1[13]);
        a0[14] = fmaf(w3.z, xx.x, a0[14]);  a1[14] = fmaf(w3.z, xx.y, a1[14]);
        a0[15] = fmaf(w3.w, xx.x, a0[15]);  a1[15] = fmaf(w3.w, xx.y, a1[15]);
    }

    // Convert to fp16 and store. og 0..3 -> U, og 4..7 -> V.
    int node0 = base + 2 * ng;
    uint4* dst = ((og < 4) ? g_U : g_V) + node0 * 8 + (og & 3) * 2;
    dst[0] = make_uint4(f2h2(a0[0],  a0[1]),  f2h2(a0[2],  a0[3]),
                        f2h2(a0[4],  a0[5]),  f2h2(a0[6],  a0[7]));
    dst[1] = make_uint4(f2h2(a0[8],  a0[9]),  f2h2(a0[10], a0[11]),
                        f2h2(a0[12], a0[13]), f2h2(a0[14], a0[15]));
    dst[8] = make_uint4(f2h2(a1[0],  a1[1]),  f2h2(a1[2],  a1[3]),
                        f2h2(a1[4],  a1[5]),  f2h2(a1[6],  a1[7]));
    dst[9] = make_uint4(f2h2(a1[8],  a1[9]),  f2h2(a1[10], a1[11]),
                        f2h2(a1[12], a1[13]), f2h2(a1[14], a1[15]));
}

// ---------------------------------------------------------------------------
// Kernel 2: per-edge combine + suppression + max over K.
// fp16 U/V gathers (half the bytes of R5), fp32 math. One warp per point,
// lanes 0..15 precompute per-k indices + suppression (shfl-distributed).
// ---------------------------------------------------------------------------
__global__ __launch_bounds__(256) void edge_kernel(const int* __restrict__ ei,
                                                   const float* __restrict__ bias,
                                                   float* __restrict__ out) {
    __shared__ float sm[8 * 66];

    int tid  = threadIdx.x;
    int warp = tid >> 5;
    int lane = tid & 31;

    int g = blockIdx.x * 8 + warp;   // 20000 % 8 == 0 -> block never crosses batch
    int b = g / NPTS;
    int n = g - b * NPTS;

    const int* e0 = ei + (b * NPTS + n) * KK;                    // neighbor idx
    const int* e1 = ei + (BB * NPTS * KK) + (b * NPTS + n) * KK; // center idx

    const __half2* Ub = reinterpret_cast<const __half2*>(g_U) + b * NPTS * 32;
    const __half2* Vb = reinterpret_cast<const __half2*>(g_V) + b * NPTS * 32;
    const float4*  Pb = reinterpret_cast<const float4*>(g_posT) + b * NPTS;

    int   i0l = 0, i1l = 0;
    float sl  = 0.0f;
    if (lane < KK) {
        i0l = e0[lane];
        i1l = e1[lane];
        float4 p1 = Pb[i1l];
        float4 p0 = Pb[i0l];
        float dx = p1.x - p0.x, dy = p1.y - p0.y, dz = p1.z - p0.z;
        float dis = sqrtf(dx * dx + dy * dy + dz * dz);
        sl = 2.0f / (1.0f + __expf(dis));   // 2*sigmoid(-dis)
    }

    float2 bb = reinterpret_cast<const float2*>(bias)[lane];

    float m0 = 0.0f, m1 = 0.0f;

#pragma unroll
    for (int k0 = 0; k0 < KK; k0 += 4) {
        __half2 u[4], v[4];
        float   s[4];
#pragma unroll
        for (int j = 0; j < 4; ++j) {
            int i1 = __shfl_sync(0xFFFFFFFFu, i1l, k0 + j);
            int i0 = __shfl_sync(0xFFFFFFFFu, i0l, k0 + j);
            s[j]   = __shfl_sync(0xFFFFFFFFu, sl,  k0 + j);
            u[j] = Ub[i1 * 32 + lane];
            v[j] = Vb[i0 * 32 + lane];
        }
#pragma unroll
        for (int j = 0; j < 4; ++j) {
            float2 uf = __half22float2(u[j]);
            float2 vf = __half22float2(v[j]);
            float y0 = fmaxf(uf.x + vf.x + bb.x, 0.0f) * s[j];
            float y1 = fmaxf(uf.y + vf.y + bb.y, 0.0f) * s[j];
            m0 = fmaxf(m0, y0);
            m1 = fmaxf(m1, y1);
        }
    }

    reinterpret_cast<float2*>(sm + warp * 66)[lane] = make_float2(m0, m1);
    __syncthreads();

    int base = blockIdx.x * 8;
    int b2 = base / NPTS;
    int n0 = base - b2 * NPTS;
#pragma unroll
    for (int e = tid; e < CO * 8; e += 256) {
        int o  = e >> 3;
        int nn = e & 7;
        out[(b2 * CO + o) * NPTS + n0 + nn] = sm[nn * 66 + o];
    }
}

extern "C" void kernel_launch(void* const* d_in, const int* in_sizes, int n_in,
                              void* d_out, int out_size) {
    const float* x    = (const float*)d_in[0];
    const int*   ei   = (const int*)d_in[1];
    const float* pos  = (const float*)d_in[2];
    const float* W    = (const float*)d_in[3];
    const float* bias = (const float*)d_in[4];
    float* out = (float*)d_out;

    wprep_kernel<<<16, 256>>>(W);
    uv_kernel<<<NODES / 64, 256>>>(x, pos);
    edge_kernel<<<NODES / 8, 256>>>(ei, bias, out);
}